// round 2
// baseline (speedup 1.0000x reference)
#include <cuda_runtime.h>

#define EPS 1e-7f
#define NDIM 64
#define MAXN 32768
#define MAXR 2048
#define MAXCHUNKS 128
#define TPB 128   // main kernel threads per block
#define RPT 4     // r values per thread (2 f32x2 packs)

// ---------------- device scratch (no allocations allowed) ----------------
__device__ float2 g_pts[MAXN];                 // sorted by dim: (-t_masked, v)
__device__ int    g_choff[NDIM + 1];           // dim offsets into g_pts
__device__ int    g_chunkhist[MAXCHUNKS][NDIM];
__device__ int    g_chunkbase[MAXCHUNKS][NDIM];
__device__ float  g_sumv[NDIM];                // sum of v per dim (all points)
__device__ float  g_Sws [NDIM * MAXR];         // sum e            [d][r]
__device__ float  g_Swsv[NDIM * MAXR];         // sum e*v
__device__ float  g_Swc [NDIM * MAXR];         // sum e^10
__device__ float  g_Swcv[NDIM * MAXR];         // sum e^10*v

// ---------------- f32x2 packed helpers (sm_100a) ----------------
typedef unsigned long long ull;

__device__ __forceinline__ ull pack2(float lo, float hi) {
    ull r; asm("mov.b64 %0, {%1, %2};" : "=l"(r) : "f"(lo), "f"(hi)); return r;
}
__device__ __forceinline__ void unpack2(ull p, float& lo, float& hi) {
    asm("mov.b64 {%0, %1}, %2;" : "=f"(lo), "=f"(hi) : "l"(p));
}
__device__ __forceinline__ ull add2(ull a, ull b) {
    ull r; asm("add.rn.f32x2 %0, %1, %2;" : "=l"(r) : "l"(a), "l"(b)); return r;
}
__device__ __forceinline__ ull mul2(ull a, ull b) {
    ull r; asm("mul.rn.f32x2 %0, %1, %2;" : "=l"(r) : "l"(a), "l"(b)); return r;
}
__device__ __forceinline__ ull fma2(ull a, ull b, ull c) {
    ull r; asm("fma.rn.f32x2 %0, %1, %2, %3;" : "=l"(r) : "l"(a), "l"(b), "l"(c)); return r;
}
__device__ __forceinline__ float ex2f(float x) {
    float y; asm("ex2.approx.f32 %0, %1;" : "=f"(y) : "f"(x)); return y;
}

// ---------------- P1: per-chunk histogram (deterministic: int adds) ----------------
__global__ void k_hist(const float* __restrict__ S, int n) {
    __shared__ int h[NDIM];
    int tid = threadIdx.x;
    if (tid < NDIM) h[tid] = 0;
    __syncthreads();
    int i = blockIdx.x * 256 + tid;
    if (i < n) {
        int d = (int)S[i * 3 + 2];
        atomicAdd(&h[d], 1);
    }
    __syncthreads();
    if (tid < NDIM) g_chunkhist[blockIdx.x][tid] = h[tid];
}

// ---------------- P2: scan chunk histograms -> dim offsets + chunk bases ----------------
__global__ void k_scan(int nchunks) {
    int d = threadIdx.x;  // 64 threads
    int run = 0;
    for (int c = 0; c < nchunks; c++) {
        g_chunkbase[c][d] = run;
        run += g_chunkhist[c][d];
    }
    __shared__ int tot[NDIM];
    tot[d] = run;
    __syncthreads();
    int off = 0;
    for (int k = 0; k < d; k++) off += tot[k];
    g_choff[d] = off;
    if (d == NDIM - 1) g_choff[NDIM] = off + run;
    for (int c = 0; c < nchunks; c++) g_chunkbase[c][d] += off;
}

// ---------------- P3: stable scatter into dim-sorted order ----------------
__global__ void k_scatter(const float* __restrict__ S, int n) {
    __shared__ float st[256], sv[256];
    __shared__ int   sd[256], sp[256];
    int tid = threadIdx.x;
    int i = blockIdx.x * 256 + tid;
    if (i < n) {
        st[tid] = S[i * 3 + 0];
        sv[tid] = S[i * 3 + 1];
        sd[tid] = (int)S[i * 3 + 2];
    } else {
        sd[tid] = -1;
    }
    __syncthreads();
    if (tid < NDIM) {  // thread d assigns stable ranks for dim d
        int cnt = g_chunkbase[blockIdx.x][tid];
        for (int j = 0; j < 256; j++)
            if (sd[j] == tid) sp[j] = cnt++;
    }
    __syncthreads();
    if (i < n) {
        float t = st[tid];
        float tm = (t > 0.0f) ? t : 1.0e9f;  // masked points -> exp underflows to 0
        g_pts[sp[tid]] = make_float2(-tm, sv[tid]);  // store -t so dt = r + (-t)
    }
}

// ---------------- P4: per-dim sum of v (deterministic tree reduction) ----------------
__global__ void k_sumv() {
    int d = blockIdx.x;
    int tid = threadIdx.x;  // 128 threads
    int lo = g_choff[d], hi = g_choff[d + 1];
    float s = 0.0f;
    for (int i = lo + tid; i < hi; i += 128) s += g_pts[i].y;
    __shared__ float sm[128];
    sm[tid] = s;
    __syncthreads();
    for (int w = 64; w > 0; w >>= 1) {
        if (tid < w) sm[tid] += sm[tid + w];
        __syncthreads();
    }
    if (tid == 0) g_sumv[d] = sm[0];
}

// ---------------- main: 67M-pair kernel, packed f32x2, 4 r's per thread ----------------
__global__ void __launch_bounds__(TPB) k_main(const float* __restrict__ ref,
                                              const float* __restrict__ alpha,
                                              int R) {
    const int d   = blockIdx.y;
    const int lo  = g_choff[d];
    const int hi  = g_choff[d + 1];
    const int tid = threadIdx.x;
    const int r0  = blockIdx.x * (TPB * RPT) + tid;  // r0, r0+TPB, r0+2TPB, r0+3TPB

    const float a    = __ldg(alpha);
    const float negC = -a * 1.4426950408889634f;     // -alpha * log2(e)
    const ull  negC2 = pack2(negC, negC);

    const ull rr01 = pack2(__ldg(ref + r0),            __ldg(ref + r0 + TPB));
    const ull rr23 = pack2(__ldg(ref + r0 + 2 * TPB),  __ldg(ref + r0 + 3 * TPB));

    ull ws01 = 0, wsv01 = 0, wc01 = 0, wcv01 = 0;
    ull ws23 = 0, wsv23 = 0, wc23 = 0, wcv23 = 0;

#pragma unroll 4
    for (int i = lo; i < hi; i++) {
        float2 p = __ldg(&g_pts[i]);          // warp-uniform broadcast load
        ull tp = pack2(p.x, p.x);             // {-t, -t}
        ull vp = pack2(p.y, p.y);             // { v,  v}

        ull dt01 = add2(rr01, tp);
        ull dt23 = add2(rr23, tp);
        ull q01  = mul2(dt01, dt01);          // dt^2
        ull q23  = mul2(dt23, dt23);
        ull g01  = mul2(q01, negC2);          // log2-domain arg
        ull g23  = mul2(q23, negC2);

        float a0, a1, a2, a3;
        unpack2(g01, a0, a1);
        unpack2(g23, a2, a3);
        ull e01 = pack2(ex2f(a0), ex2f(a1));  // e = exp(-a*dt^2)
        ull e23 = pack2(ex2f(a2), ex2f(a3));

        // e^10 = ((e^2)^2)^2 * e^2  (4 packed muls, avoids a 2nd EX2)
        ull t2a = mul2(e01, e01);
        ull t4a = mul2(t2a, t2a);
        ull t8a = mul2(t4a, t4a);
        ull ec01 = mul2(t8a, t2a);
        ull t2b = mul2(e23, e23);
        ull t4b = mul2(t2b, t2b);
        ull t8b = mul2(t4b, t4b);
        ull ec23 = mul2(t8b, t2b);

        ws01  = add2(ws01, e01);
        wsv01 = fma2(e01, vp, wsv01);
        wc01  = add2(wc01, ec01);
        wcv01 = fma2(ec01, vp, wcv01);
        ws23  = add2(ws23, e23);
        wsv23 = fma2(e23, vp, wsv23);
        wc23  = add2(wc23, ec23);
        wcv23 = fma2(ec23, vp, wcv23);
    }

    float x0, x1;
    const int base = d * R + r0;
    unpack2(ws01,  x0, x1); g_Sws [base] = x0; g_Sws [base + TPB] = x1;
    unpack2(ws23,  x0, x1); g_Sws [base + 2 * TPB] = x0; g_Sws [base + 3 * TPB] = x1;
    unpack2(wsv01, x0, x1); g_Swsv[base] = x0; g_Swsv[base + TPB] = x1;
    unpack2(wsv23, x0, x1); g_Swsv[base + 2 * TPB] = x0; g_Swsv[base + 3 * TPB] = x1;
    unpack2(wc01,  x0, x1); g_Swc [base] = x0; g_Swc [base + TPB] = x1;
    unpack2(wc23,  x0, x1); g_Swc [base + 2 * TPB] = x0; g_Swc [base + 3 * TPB] = x1;
    unpack2(wcv01, x0, x1); g_Swcv[base] = x0; g_Swcv[base + TPB] = x1;
    unpack2(wcv23, x0, x1); g_Swcv[base + 2 * TPB] = x0; g_Swcv[base + 3 * TPB] = x1;
}

// ---------------- finalize: EPS terms, rho matvec, output assembly ----------------
__global__ void k_finalize(const float* __restrict__ rho,
                           float* __restrict__ out,
                           int R, float Rinv) {
    const int r = blockIdx.x;
    const int d = threadIdx.x;  // 64 threads

    const int cnt   = g_choff[d + 1] - g_choff[d];
    const float ec  = EPS * (float)(cnt + 1);   // EPS per Ks entry + trailing +EPS
    const float ev  = EPS * g_sumv[d];          // EPS * sum(v) in this dim

    const float lam_s = g_Sws [d * R + r] + ec;
    const float ksv   = g_Swsv[d * R + r] + ev;  // (Ks @ wv)[r,d]
    const float lam_c = g_Swc [d * R + r] + ec;
    const float kcv   = g_Swcv[d * R + r] + ev;

    __shared__ float s_ksv[NDIM], s_lam[NDIM];
    s_ksv[d] = ksv;
    s_lam[d] = lam_s;
    __syncthreads();

    float denom = 0.0f;
#pragma unroll
    for (int k = 0; k < NDIM; k++) denom += s_lam[k];

    float cr = 0.0f;
#pragma unroll
    for (int k = 0; k < NDIM; k++)
        cr = fmaf(s_ksv[k], __ldg(&rho[k * NDIM + d]), cr);
    cr = __fdividef(cr, denom);   // cross[r,d]: /R factors cancel

    const float coarse = __fdividef(kcv, lam_c);

    float* o = out + (long long)r * (3 * NDIM);
    o[d]             = lam_s * Rinv;     // lam
    o[NDIM + d]      = cr;               // cross
    o[2 * NDIM + d]  = coarse - cr;      // transient
}

// ---------------- launch ----------------
extern "C" void kernel_launch(void* const* d_in, const int* in_sizes, int n_in,
                              void* d_out, int out_size) {
    const float* S     = (const float*)d_in[0];
    const float* ref   = (const float*)d_in[1];
    const float* alpha = (const float*)d_in[2];
    const float* rho   = (const float*)d_in[3];
    const int n = in_sizes[0] / 3;
    const int R = in_sizes[1];
    int nchunks = (n + 255) / 256;
    if (nchunks > MAXCHUNKS) nchunks = MAXCHUNKS;

    k_hist<<<nchunks, 256>>>(S, n);
    k_scan<<<1, NDIM>>>(nchunks);
    k_scatter<<<nchunks, 256>>>(S, n);
    k_sumv<<<NDIM, 128>>>();

    dim3 g(R / (TPB * RPT), NDIM);
    k_main<<<g, TPB>>>(ref, alpha, R);

    k_finalize<<<R, NDIM>>>(rho, (float*)d_out, R, 1.0f / (float)R);
}

// round 3
// speedup vs baseline: 1.1879x; 1.1879x over previous
#include <cuda_runtime.h>

#define EPS 1e-7f
#define NDIM 64
#define MAXN 32768
#define MAXR 2048
#define MAXCHUNKS 128
#define TPB 256   // main kernel threads per block
#define RPT 4     // r values per thread (2 f32x2 packs)
#define VSCALE 8388608.0f      // 2^23 fixed-point scale for deterministic v-sums
#define VSCALE_INV 1.1920928955078125e-7f  // 2^-23

// ---------------- device scratch (no allocations allowed) ----------------
__device__ float2 g_pts[MAXN];                 // sorted by dim: (-t_masked, v)
__device__ int    g_choff[NDIM + 1];           // dim offsets into g_pts
__device__ int    g_chunkhist[MAXCHUNKS][NDIM];
__device__ unsigned long long g_chunkvsum[MAXCHUNKS][NDIM];  // fixed-point v sums
__device__ float  g_sumv[NDIM];                // sum of v per dim (all points)
__device__ float  g_Sws [NDIM * MAXR];         // sum e            [d][r]
__device__ float  g_Swsv[NDIM * MAXR];         // sum e*v
__device__ float  g_Swc [NDIM * MAXR];         // sum e^10
__device__ float  g_Swcv[NDIM * MAXR];         // sum e^10*v

// ---------------- f32x2 packed helpers (sm_100a) ----------------
typedef unsigned long long ull;

__device__ __forceinline__ ull pack2(float lo, float hi) {
    ull r; asm("mov.b64 %0, {%1, %2};" : "=l"(r) : "f"(lo), "f"(hi)); return r;
}
__device__ __forceinline__ void unpack2(ull p, float& lo, float& hi) {
    asm("mov.b64 {%0, %1}, %2;" : "=f"(lo), "=f"(hi) : "l"(p));
}
__device__ __forceinline__ ull add2(ull a, ull b) {
    ull r; asm("add.rn.f32x2 %0, %1, %2;" : "=l"(r) : "l"(a), "l"(b)); return r;
}
__device__ __forceinline__ ull mul2(ull a, ull b) {
    ull r; asm("mul.rn.f32x2 %0, %1, %2;" : "=l"(r) : "l"(a), "l"(b)); return r;
}
__device__ __forceinline__ ull fma2(ull a, ull b, ull c) {
    ull r; asm("fma.rn.f32x2 %0, %1, %2, %3;" : "=l"(r) : "l"(a), "l"(b), "l"(c)); return r;
}
__device__ __forceinline__ float ex2f(float x) {
    float y; asm("ex2.approx.f32 %0, %1;" : "=f"(y) : "f"(x)); return y;
}

// ---------------- P1: per-chunk histogram + fixed-point v sums ----------------
__global__ void k_hist(const float* __restrict__ S, int n) {
    __shared__ int h[NDIM];
    __shared__ unsigned long long vs[NDIM];
    int tid = threadIdx.x;
    if (tid < NDIM) { h[tid] = 0; vs[tid] = 0ULL; }
    __syncthreads();
    int i = blockIdx.x * 256 + tid;
    if (i < n) {
        int d = (int)S[i * 3 + 2];
        float v = S[i * 3 + 1];
        atomicAdd(&h[d], 1);
        long long fx = llrintf(v * VSCALE);
        atomicAdd(&vs[d], (unsigned long long)fx);   // 2's-complement wrap = exact int sum
    }
    __syncthreads();
    if (tid < NDIM) {
        g_chunkhist[blockIdx.x][tid] = h[tid];
        g_chunkvsum[blockIdx.x][tid] = vs[tid];
    }
}

// ---------------- P2: stable scatter (each block recomputes the scan) ----------------
__global__ void k_scatter(const float* __restrict__ S, int n, int nchunks) {
    __shared__ float st[256], sv[256];
    __shared__ int   sd[256], sp[256];
    __shared__ int   s_tot[NDIM], s_base[NDIM];
    const int tid = threadIdx.x;
    const int c   = blockIdx.x;

    // local scan: thread d computes total[d] and count-before-chunk-c[d]
    if (tid < NDIM) {
        int before = 0, total = 0;
        for (int cc = 0; cc < nchunks; cc++) {
            int hv = g_chunkhist[cc][tid];
            total += hv;
            if (cc < c) before += hv;
        }
        s_tot[tid] = total;
        s_base[tid] = before;
    }
    __syncthreads();
    if (tid < NDIM) {
        int off = 0;
        for (int k = 0; k < tid; k++) off += s_tot[k];
        s_base[tid] += off;
        if (c == 0) {                       // block 0 publishes dim offsets + sumv
            g_choff[tid] = off;
            if (tid == NDIM - 1) g_choff[NDIM] = off + s_tot[tid];
            unsigned long long acc = 0ULL;
            for (int cc = 0; cc < nchunks; cc++) acc += g_chunkvsum[cc][tid];
            g_sumv[tid] = (float)((long long)acc) * VSCALE_INV;
        }
    }

    // stage chunk
    int i = c * 256 + tid;
    if (i < n) {
        st[tid] = S[i * 3 + 0];
        sv[tid] = S[i * 3 + 1];
        sd[tid] = (int)S[i * 3 + 2];
    } else {
        sd[tid] = -1;
    }
    __syncthreads();
    if (tid < NDIM) {  // thread d assigns stable ranks for dim d
        int cnt = s_base[tid];
        for (int j = 0; j < 256; j++)
            if (sd[j] == tid) sp[j] = cnt++;
    }
    __syncthreads();
    if (i < n) {
        float t = st[tid];
        float tm = (t > 0.0f) ? t : 1.0e9f;         // masked -> exp underflows to 0
        g_pts[sp[tid]] = make_float2(-tm, sv[tid]); // store -t so dt = r + (-t)
    }
}

// ---------------- main: 67M-pair kernel, packed f32x2, 4 r's per thread ----------------
// grid = (R/(TPB*RPT)=2, NDIM) = 128 CTAs of 256 threads -> 1 wave, 2 warps/SMSP
__global__ void __launch_bounds__(TPB) k_main(const float* __restrict__ ref,
                                              const float* __restrict__ alpha,
                                              int R) {
    const int d   = blockIdx.y;
    const int lo  = g_choff[d];
    const int hi  = g_choff[d + 1];
    const int tid = threadIdx.x;
    const int r0  = blockIdx.x * (TPB * RPT) + tid;  // r0, r0+TPB, r0+2TPB, r0+3TPB

    const float a    = __ldg(alpha);
    const float negC = -a * 1.4426950408889634f;     // -alpha * log2(e)
    const ull  negC2 = pack2(negC, negC);

    const ull rr01 = pack2(__ldg(ref + r0),            __ldg(ref + r0 + TPB));
    const ull rr23 = pack2(__ldg(ref + r0 + 2 * TPB),  __ldg(ref + r0 + 3 * TPB));

    ull ws01 = 0, wsv01 = 0, wc01 = 0, wcv01 = 0;
    ull ws23 = 0, wsv23 = 0, wc23 = 0, wcv23 = 0;

#pragma unroll 4
    for (int i = lo; i < hi; i++) {
        float2 p = __ldg(&g_pts[i]);          // warp-uniform broadcast load
        ull tp = pack2(p.x, p.x);             // {-t, -t}
        ull vp = pack2(p.y, p.y);             // { v,  v}

        ull dt01 = add2(rr01, tp);
        ull dt23 = add2(rr23, tp);
        ull q01  = mul2(dt01, dt01);          // dt^2
        ull q23  = mul2(dt23, dt23);
        ull g01  = mul2(q01, negC2);          // log2-domain arg
        ull g23  = mul2(q23, negC2);

        float a0, a1, a2, a3;
        unpack2(g01, a0, a1);
        unpack2(g23, a2, a3);
        ull e01 = pack2(ex2f(a0), ex2f(a1));  // e = exp(-a*dt^2)
        ull e23 = pack2(ex2f(a2), ex2f(a3));

        // e^10 = ((e^2)^2)^2 * e^2  (4 packed muls, avoids a 2nd EX2)
        ull t2a = mul2(e01, e01);
        ull t4a = mul2(t2a, t2a);
        ull t8a = mul2(t4a, t4a);
        ull ec01 = mul2(t8a, t2a);
        ull t2b = mul2(e23, e23);
        ull t4b = mul2(t2b, t2b);
        ull t8b = mul2(t4b, t4b);
        ull ec23 = mul2(t8b, t2b);

        ws01  = add2(ws01, e01);
        wsv01 = fma2(e01, vp, wsv01);
        wc01  = add2(wc01, ec01);
        wcv01 = fma2(ec01, vp, wcv01);
        ws23  = add2(ws23, e23);
        wsv23 = fma2(e23, vp, wsv23);
        wc23  = add2(wc23, ec23);
        wcv23 = fma2(ec23, vp, wcv23);
    }

    float x0, x1;
    const int base = d * R + r0;
    unpack2(ws01,  x0, x1); g_Sws [base] = x0; g_Sws [base + TPB] = x1;
    unpack2(ws23,  x0, x1); g_Sws [base + 2 * TPB] = x0; g_Sws [base + 3 * TPB] = x1;
    unpack2(wsv01, x0, x1); g_Swsv[base] = x0; g_Swsv[base + TPB] = x1;
    unpack2(wsv23, x0, x1); g_Swsv[base + 2 * TPB] = x0; g_Swsv[base + 3 * TPB] = x1;
    unpack2(wc01,  x0, x1); g_Swc [base] = x0; g_Swc [base + TPB] = x1;
    unpack2(wc23,  x0, x1); g_Swc [base + 2 * TPB] = x0; g_Swc [base + 3 * TPB] = x1;
    unpack2(wcv01, x0, x1); g_Swcv[base] = x0; g_Swcv[base + TPB] = x1;
    unpack2(wcv23, x0, x1); g_Swcv[base + 2 * TPB] = x0; g_Swcv[base + 3 * TPB] = x1;
}

// ---------------- finalize: EPS terms, rho matvec, output assembly ----------------
// 256 threads = 4 r's per block (rl = tid/64, d = tid%64), grid = R/4
__global__ void k_finalize(const float* __restrict__ rho,
                           float* __restrict__ out,
                           int R, float Rinv) {
    const int tid = threadIdx.x;
    const int rl  = tid >> 6;
    const int d   = tid & 63;
    const int r   = blockIdx.x * 4 + rl;

    const int cnt   = g_choff[d + 1] - g_choff[d];
    const float ec  = EPS * (float)(cnt + 1);   // EPS per Ks entry + trailing +EPS
    const float ev  = EPS * g_sumv[d];          // EPS * sum(v) in this dim

    const float lam_s = g_Sws [d * R + r] + ec;
    const float ksv   = g_Swsv[d * R + r] + ev;  // (Ks @ wv)[r,d]
    const float lam_c = g_Swc [d * R + r] + ec;
    const float kcv   = g_Swcv[d * R + r] + ev;

    __shared__ float s_ksv[4][NDIM], s_lam[4][NDIM];
    s_ksv[rl][d] = ksv;
    s_lam[rl][d] = lam_s;
    __syncthreads();

    float denom = 0.0f;
#pragma unroll
    for (int k = 0; k < NDIM; k++) denom += s_lam[rl][k];

    float cr = 0.0f;
#pragma unroll
    for (int k = 0; k < NDIM; k++)
        cr = fmaf(s_ksv[rl][k], __ldg(&rho[k * NDIM + d]), cr);
    cr = __fdividef(cr, denom);   // cross[r,d]: /R factors cancel

    const float coarse = __fdividef(kcv, lam_c);

    float* o = out + (long long)r * (3 * NDIM);
    o[d]             = lam_s * Rinv;     // lam
    o[NDIM + d]      = cr;               // cross
    o[2 * NDIM + d]  = coarse - cr;      // transient
}

// ---------------- launch ----------------
extern "C" void kernel_launch(void* const* d_in, const int* in_sizes, int n_in,
                              void* d_out, int out_size) {
    const float* S     = (const float*)d_in[0];
    const float* ref   = (const float*)d_in[1];
    const float* alpha = (const float*)d_in[2];
    const float* rho   = (const float*)d_in[3];
    const int n = in_sizes[0] / 3;
    const int R = in_sizes[1];
    int nchunks = (n + 255) / 256;
    if (nchunks > MAXCHUNKS) nchunks = MAXCHUNKS;

    k_hist<<<nchunks, 256>>>(S, n);
    k_scatter<<<nchunks, 256>>>(S, n, nchunks);

    dim3 g(R / (TPB * RPT), NDIM);
    k_main<<<g, TPB>>>(ref, alpha, R);

    k_finalize<<<R / 4, 256>>>(rho, (float*)d_out, R, 1.0f / (float)R);
}

// round 5
// speedup vs baseline: 1.4615x; 1.2304x over previous
#include <cuda_runtime.h>

#define EPS 1e-7f
#define NDIM 64
#define MAXN 32768
#define MAXR 2048
#define MAXCHUNKS 128
#define TPB 128   // main kernel threads per block
#define RPT 4     // r values per thread (2 f32x2 packs)
#define LOG2E 1.4426950408889634f
#define VSCALE 8388608.0f                  // 2^23 fixed-point scale for v-sums
#define VSCALE_INV 1.1920928955078125e-7f  // 2^-23
#define RT 16     // r's per finalize block

typedef unsigned long long ull;

// ---------------- device scratch (no allocations allowed) ----------------
__device__ ulonglong2 g_bc[MAXN];              // prepacked {B,B},{C,C} per point (dim-sorted)
__device__ ull    g_vv[MAXN];                  // prepacked {v,v}
__device__ int    g_choff[NDIM + 1];           // dim offsets
__device__ int    g_chunkhist[MAXCHUNKS][NDIM];
__device__ ull    g_chunkvsum[MAXCHUNKS][NDIM];
__device__ float  g_sumv[NDIM];
__device__ float  g_Sws [2][NDIM * MAXR];      // sum e        [half][d][r]
__device__ float  g_Swsv[2][NDIM * MAXR];      // sum e*v
__device__ float  g_Swc [2][NDIM * MAXR];      // sum e^10
__device__ float  g_Swcv[2][NDIM * MAXR];      // sum e^10*v

// ---------------- f32x2 packed helpers (sm_100a) ----------------
__device__ __forceinline__ ull pack2(float lo, float hi) {
    ull r; asm("mov.b64 %0, {%1, %2};" : "=l"(r) : "f"(lo), "f"(hi)); return r;
}
__device__ __forceinline__ void unpack2(ull p, float& lo, float& hi) {
    asm("mov.b64 {%0, %1}, %2;" : "=f"(lo), "=f"(hi) : "l"(p));
}
__device__ __forceinline__ ull add2(ull a, ull b) {
    ull r; asm("add.rn.f32x2 %0, %1, %2;" : "=l"(r) : "l"(a), "l"(b)); return r;
}
__device__ __forceinline__ ull mul2(ull a, ull b) {
    ull r; asm("mul.rn.f32x2 %0, %1, %2;" : "=l"(r) : "l"(a), "l"(b)); return r;
}
__device__ __forceinline__ ull fma2(ull a, ull b, ull c) {
    ull r; asm("fma.rn.f32x2 %0, %1, %2, %3;" : "=l"(r) : "l"(a), "l"(b), "l"(c)); return r;
}
__device__ __forceinline__ float ex2f(float x) {
    float y; asm("ex2.approx.f32 %0, %1;" : "=f"(y) : "f"(x)); return y;
}

// ---------------- P1: per-chunk histogram + fixed-point v sums ----------------
__global__ void k_hist(const float* __restrict__ S, int n) {
    __shared__ int h[NDIM];
    __shared__ ull vs[NDIM];
    int tid = threadIdx.x;
    if (tid < NDIM) { h[tid] = 0; vs[tid] = 0ULL; }
    __syncthreads();
    int i = blockIdx.x * 256 + tid;
    if (i < n) {
        int d = (int)S[i * 3 + 2];
        float v = S[i * 3 + 1];
        atomicAdd(&h[d], 1);
        long long fx = llrintf(v * VSCALE);
        atomicAdd(&vs[d], (ull)fx);   // 2's-complement wrap = exact int sum
    }
    __syncthreads();
    if (tid < NDIM) {
        g_chunkhist[blockIdx.x][tid] = h[tid];
        g_chunkvsum[blockIdx.x][tid] = vs[tid];
    }
}

// ---------------- P2: stable scatter + point preprocessing ----------------
__global__ void k_scatter(const float* __restrict__ S,
                          const float* __restrict__ alpha,
                          int n, int nchunks) {
    __shared__ float st[256], sv[256];
    __shared__ int   sd[256], sp[256];
    __shared__ int   s_tot[NDIM], s_base[NDIM];
    const int tid = threadIdx.x;
    const int c   = blockIdx.x;

    if (tid < NDIM) {
        int before = 0, total = 0;
        for (int cc = 0; cc < nchunks; cc++) {
            int hv = g_chunkhist[cc][tid];
            total += hv;
            if (cc < c) before += hv;
        }
        s_tot[tid] = total;
        s_base[tid] = before;
    }
    __syncthreads();
    if (tid < NDIM) {
        int off = 0;
        for (int k = 0; k < tid; k++) off += s_tot[k];
        s_base[tid] += off;
        if (c == 0) {
            g_choff[tid] = off;
            if (tid == NDIM - 1) g_choff[NDIM] = off + s_tot[tid];
            ull acc = 0ULL;
            for (int cc = 0; cc < nchunks; cc++) acc += g_chunkvsum[cc][tid];
            g_sumv[tid] = (float)((long long)acc) * VSCALE_INV;
        }
    }

    int i = c * 256 + tid;
    if (i < n) {
        st[tid] = S[i * 3 + 0];
        sv[tid] = S[i * 3 + 1];
        sd[tid] = (int)S[i * 3 + 2];
    } else {
        sd[tid] = -1;
    }
    __syncthreads();
    if (tid < NDIM) {
        int cnt = s_base[tid];
        for (int j = 0; j < 256; j++)
            if (sd[j] == tid) sp[j] = cnt++;
    }
    __syncthreads();
    if (i < n) {
        float t = st[tid];
        float tm = (t > 0.0f) ? t : 1.0e9f;     // masked -> exp underflows to 0
        float negC = -__ldg(alpha) * LOG2E;     // -alpha*log2(e)
        float B = -2.0f * negC * tm;            // arg = negC*(r-t)^2 = A + B*r + C
        float Cc = negC * tm * tm;
        ulonglong2 bc;
        bc.x = pack2(B, B);
        bc.y = pack2(Cc, Cc);
        int pos = sp[tid];
        g_bc[pos] = bc;
        g_vv[pos] = pack2(sv[tid], sv[tid]);
    }
}

// ---------------- main: 67M-pair kernel ----------------
// grid = (R/(TPB*RPT)=4, NDIM, 2 point-halves) = 512 CTAs of 128 threads
__global__ void __launch_bounds__(TPB) k_main(const float* __restrict__ ref,
                                              const float* __restrict__ alpha,
                                              int R) {
    const int d   = blockIdx.y;
    const int lo0 = g_choff[d];
    const int hi0 = g_choff[d + 1];
    const int mid = lo0 + ((hi0 - lo0) >> 1);
    const int lo  = blockIdx.z ? mid : lo0;
    const int hi  = blockIdx.z ? hi0 : mid;
    const int tid = threadIdx.x;
    const int r0  = blockIdx.x * (TPB * RPT) + tid;

    const float negC = -__ldg(alpha) * LOG2E;
    const float f0 = __ldg(ref + r0),           f1 = __ldg(ref + r0 + TPB);
    const float f2 = __ldg(ref + r0 + 2 * TPB), f3 = __ldg(ref + r0 + 3 * TPB);
    const ull rr01 = pack2(f0, f1);
    const ull rr23 = pack2(f2, f3);
    const ull A01  = pack2(negC * f0 * f0, negC * f1 * f1);  // A = negC*r^2
    const ull A23  = pack2(negC * f2 * f2, negC * f3 * f3);

    ull ws01 = 0, wsv01 = 0, wc01 = 0, wcv01 = 0;
    ull ws23 = 0, wsv23 = 0, wc23 = 0, wcv23 = 0;

#pragma unroll 4
    for (int i = lo; i < hi; i++) {
        ulonglong2 bc = __ldg(&g_bc[i]);      // {B,B},{C,C}
        ull vp = __ldg(&g_vv[i]);             // {v,v}

        ull pc01 = add2(bc.y, A01);           // C + A
        ull pc23 = add2(bc.y, A23);
        ull g01  = fma2(bc.x, rr01, pc01);    // arg = B*r + (C+A) = negC*(r-t)^2
        ull g23  = fma2(bc.x, rr23, pc23);

        float a0, a1, a2, a3;
        unpack2(g01, a0, a1);
        unpack2(g23, a2, a3);
        ull e01 = pack2(ex2f(a0), ex2f(a1));  // e = exp(-a*dt^2)
        ull e23 = pack2(ex2f(a2), ex2f(a3));

        // e^10 = ((e^2)^2)^2 * e^2
        ull t2a = mul2(e01, e01);
        ull t4a = mul2(t2a, t2a);
        ull t8a = mul2(t4a, t4a);
        ull ec01 = mul2(t8a, t2a);
        ull t2b = mul2(e23, e23);
        ull t4b = mul2(t2b, t2b);
        ull t8b = mul2(t4b, t4b);
        ull ec23 = mul2(t8b, t2b);

        ws01  = add2(ws01, e01);
        wsv01 = fma2(e01, vp, wsv01);
        wc01  = add2(wc01, ec01);
        wcv01 = fma2(ec01, vp, wcv01);
        ws23  = add2(ws23, e23);
        wsv23 = fma2(e23, vp, wsv23);
        wc23  = add2(wc23, ec23);
        wcv23 = fma2(ec23, vp, wcv23);
    }

    float x0, x1;
    const int h    = blockIdx.z;
    const int base = d * R + r0;
    unpack2(ws01,  x0, x1); g_Sws [h][base] = x0; g_Sws [h][base + TPB] = x1;
    unpack2(ws23,  x0, x1); g_Sws [h][base + 2 * TPB] = x0; g_Sws [h][base + 3 * TPB] = x1;
    unpack2(wsv01, x0, x1); g_Swsv[h][base] = x0; g_Swsv[h][base + TPB] = x1;
    unpack2(wsv23, x0, x1); g_Swsv[h][base + 2 * TPB] = x0; g_Swsv[h][base + 3 * TPB] = x1;
    unpack2(wc01,  x0, x1); g_Swc [h][base] = x0; g_Swc [h][base + TPB] = x1;
    unpack2(wc23,  x0, x1); g_Swc [h][base + 2 * TPB] = x0; g_Swc [h][base + 3 * TPB] = x1;
    unpack2(wcv01, x0, x1); g_Swcv[h][base] = x0; g_Swcv[h][base + TPB] = x1;
    unpack2(wcv23, x0, x1); g_Swcv[h][base + 2 * TPB] = x0; g_Swcv[h][base + 3 * TPB] = x1;
}

// ---------------- finalize: tiled/coalesced, rho matvec, output ----------------
// block = 256 threads, handles RT=16 r's; grid = R/RT
__global__ void __launch_bounds__(256) k_finalize(const float* __restrict__ rho,
                                                  float* __restrict__ out,
                                                  int R, float Rinv) {
    __shared__ float s_ksv[NDIM][RT + 1];
    __shared__ float s_lam[NDIM][RT + 1];
    __shared__ float s_coa[NDIM][RT + 1];
    __shared__ float s_rho[NDIM * NDIM];
    __shared__ float s_den[RT];

    const int tid = threadIdx.x;
    const int r0  = blockIdx.x * RT;

    // load rho (coalesced)
    for (int i = tid; i < NDIM * NDIM; i += 256) s_rho[i] = __ldg(&rho[i]);

    // tile fill: thread -> (d-pass, r). warp covers 2 d-rows x 16 r (coalesced 64B runs)
    {
        const int rr = tid & (RT - 1);
        const int dp = tid >> 4;            // 16 d-rows per pass, 4 passes
        for (int p = 0; p < 4; p++) {
            const int d = dp + p * 16;
            const int idx = d * R + r0 + rr;
            const int cnt = g_choff[d + 1] - g_choff[d];
            const float ec = EPS * (float)(cnt + 1);
            const float ev = EPS * g_sumv[d];
            float lam_s = g_Sws [0][idx] + g_Sws [1][idx] + ec;
            float ksv   = g_Swsv[0][idx] + g_Swsv[1][idx] + ev;
            float lam_c = g_Swc [0][idx] + g_Swc [1][idx] + ec;
            float kcv   = g_Swcv[0][idx] + g_Swcv[1][idx] + ev;
            s_lam[d][rr] = lam_s;
            s_ksv[d][rr] = ksv;
            s_coa[d][rr] = __fdividef(kcv, lam_c);
        }
    }
    __syncthreads();

    if (tid < RT) {
        float den = 0.0f;
#pragma unroll
        for (int k = 0; k < NDIM; k++) den += s_lam[k][tid];
        s_den[tid] = den;
    }
    __syncthreads();

    // compute: thread -> d = tid&63, 4 r's (rq*4 .. rq*4+3)
    const int d  = tid & 63;
    const int rq = tid >> 6;           // 0..3
    const int rb = rq * 4;
    float acc0 = 0.f, acc1 = 0.f, acc2 = 0.f, acc3 = 0.f;
#pragma unroll
    for (int k = 0; k < NDIM; k++) {
        float rk = s_rho[k * NDIM + d];
        acc0 = fmaf(s_ksv[k][rb + 0], rk, acc0);
        acc1 = fmaf(s_ksv[k][rb + 1], rk, acc1);
        acc2 = fmaf(s_ksv[k][rb + 2], rk, acc2);
        acc3 = fmaf(s_ksv[k][rb + 3], rk, acc3);
    }
#pragma unroll
    for (int j = 0; j < 4; j++) {
        const int rr = rb + j;
        const int r  = r0 + rr;
        float acc = (j == 0) ? acc0 : (j == 1) ? acc1 : (j == 2) ? acc2 : acc3;
        float cr = __fdividef(acc, s_den[rr]);
        float* o = out + (long long)r * (3 * NDIM);
        o[d]            = s_lam[d][rr] * Rinv;   // lam
        o[NDIM + d]     = cr;                    // cross
        o[2 * NDIM + d] = s_coa[d][rr] - cr;     // transient
    }
}

// ---------------- launch ----------------
extern "C" void kernel_launch(void* const* d_in, const int* in_sizes, int n_in,
                              void* d_out, int out_size) {
    const float* S     = (const float*)d_in[0];
    const float* ref   = (const float*)d_in[1];
    const float* alpha = (const float*)d_in[2];
    const float* rho   = (const float*)d_in[3];
    const int n = in_sizes[0] / 3;
    const int R = in_sizes[1];
    int nchunks = (n + 255) / 256;
    if (nchunks > MAXCHUNKS) nchunks = MAXCHUNKS;

    k_hist<<<nchunks, 256>>>(S, n);
    k_scatter<<<nchunks, 256>>>(S, alpha, n, nchunks);

    dim3 g(R / (TPB * RPT), NDIM, 2);
    k_main<<<g, TPB>>>(ref, alpha, R);

    k_finalize<<<R / RT, 256>>>(rho, (float*)d_out, R, 1.0f / (float)R);
}

// round 6
// speedup vs baseline: 1.7256x; 1.1807x over previous
#include <cuda_runtime.h>

#define EPS 1e-7f
#define NDIM 64
#define MAXN 32768
#define MAXR 2048
#define MAXCHUNKS 128
#define TPB 128   // main kernel threads per block
#define RPT 4     // r values per thread (2 f32x2 packs)
#define NSPLIT 4  // point-splits per dim (occupancy)
#define LOG2E 1.4426950408889634f
#define VSCALE 8388608.0f                  // 2^23 fixed-point scale for v-sums
#define VSCALE_INV 1.1920928955078125e-7f  // 2^-23

typedef unsigned long long ull;

// ---------------- device scratch (no allocations allowed) ----------------
__device__ ulonglong2 g_bc[MAXN];              // prepacked {B,B},{C,C} per point (dim-sorted)
__device__ ull    g_vv[MAXN];                  // prepacked {v,v}
__device__ int    g_choff[NDIM + 1];           // dim offsets
__device__ int    g_chunkhist[MAXCHUNKS][NDIM];
__device__ ull    g_chunkvsum[MAXCHUNKS][NDIM];
__device__ float  g_sumv[NDIM];
__device__ float  g_Sws [NSPLIT][NDIM * MAXR]; // sum e        [split][d][r]
__device__ float  g_Swsv[NSPLIT][NDIM * MAXR]; // sum e*v
__device__ float  g_Swc [NSPLIT][NDIM * MAXR]; // sum e^10
__device__ float  g_Swcv[NSPLIT][NDIM * MAXR]; // sum e^10*v

// ---------------- f32x2 packed helpers (sm_100a) ----------------
__device__ __forceinline__ ull pack2(float lo, float hi) {
    ull r; asm("mov.b64 %0, {%1, %2};" : "=l"(r) : "f"(lo), "f"(hi)); return r;
}
__device__ __forceinline__ void unpack2(ull p, float& lo, float& hi) {
    asm("mov.b64 {%0, %1}, %2;" : "=f"(lo), "=f"(hi) : "l"(p));
}
__device__ __forceinline__ ull add2(ull a, ull b) {
    ull r; asm("add.rn.f32x2 %0, %1, %2;" : "=l"(r) : "l"(a), "l"(b)); return r;
}
__device__ __forceinline__ ull mul2(ull a, ull b) {
    ull r; asm("mul.rn.f32x2 %0, %1, %2;" : "=l"(r) : "l"(a), "l"(b)); return r;
}
__device__ __forceinline__ ull fma2(ull a, ull b, ull c) {
    ull r; asm("fma.rn.f32x2 %0, %1, %2, %3;" : "=l"(r) : "l"(a), "l"(b), "l"(c)); return r;
}
__device__ __forceinline__ float ex2f(float x) {
    float y; asm("ex2.approx.f32 %0, %1;" : "=f"(y) : "f"(x)); return y;
}

// ---------------- P1: per-chunk histogram + fixed-point v sums ----------------
__global__ void k_hist(const float* __restrict__ S, int n) {
    __shared__ int h[NDIM];
    __shared__ ull vs[NDIM];
    int tid = threadIdx.x;
    if (tid < NDIM) { h[tid] = 0; vs[tid] = 0ULL; }
    __syncthreads();
    int i = blockIdx.x * 256 + tid;
    if (i < n) {
        int d = (int)S[i * 3 + 2];
        float v = S[i * 3 + 1];
        atomicAdd(&h[d], 1);
        long long fx = llrintf(v * VSCALE);
        atomicAdd(&vs[d], (ull)fx);   // 2's-complement wrap = exact int sum
    }
    __syncthreads();
    if (tid < NDIM) {
        g_chunkhist[blockIdx.x][tid] = h[tid];
        g_chunkvsum[blockIdx.x][tid] = vs[tid];
    }
}

// ---------------- P2: stable scatter + point preprocessing ----------------
__global__ void k_scatter(const float* __restrict__ S,
                          const float* __restrict__ alpha,
                          int n, int nchunks) {
    __shared__ float st[256], sv[256];
    __shared__ int   sd[256], sp[256];
    __shared__ int   s_tot[NDIM], s_base[NDIM];
    const int tid = threadIdx.x;
    const int c   = blockIdx.x;

    if (tid < NDIM) {
        int before = 0, total = 0;
        for (int cc = 0; cc < nchunks; cc++) {
            int hv = g_chunkhist[cc][tid];
            total += hv;
            if (cc < c) before += hv;
        }
        s_tot[tid] = total;
        s_base[tid] = before;
    }
    __syncthreads();
    if (tid < NDIM) {
        int off = 0;
        for (int k = 0; k < tid; k++) off += s_tot[k];
        s_base[tid] += off;
        if (c == 0) {
            g_choff[tid] = off;
            if (tid == NDIM - 1) g_choff[NDIM] = off + s_tot[tid];
            ull acc = 0ULL;
            for (int cc = 0; cc < nchunks; cc++) acc += g_chunkvsum[cc][tid];
            g_sumv[tid] = (float)((long long)acc) * VSCALE_INV;
        }
    }

    int i = c * 256 + tid;
    if (i < n) {
        st[tid] = S[i * 3 + 0];
        sv[tid] = S[i * 3 + 1];
        sd[tid] = (int)S[i * 3 + 2];
    } else {
        sd[tid] = -1;
    }
    __syncthreads();
    if (tid < NDIM) {
        int cnt = s_base[tid];
        for (int j = 0; j < 256; j++)
            if (sd[j] == tid) sp[j] = cnt++;
    }
    __syncthreads();
    if (i < n) {
        float t = st[tid];
        float tm = (t > 0.0f) ? t : 1.0e9f;     // masked -> exp underflows to 0
        float negC = -__ldg(alpha) * LOG2E;     // -alpha*log2(e)
        float B = -2.0f * negC * tm;            // arg = negC*(r-t)^2 = A + B*r + C
        float Cc = negC * tm * tm;
        ulonglong2 bc;
        bc.x = pack2(B, B);
        bc.y = pack2(Cc, Cc);
        int pos = sp[tid];
        g_bc[pos] = bc;
        g_vv[pos] = pack2(sv[tid], sv[tid]);
    }
}

// ---------------- main: 67M-pair kernel ----------------
// grid = (R/(TPB*RPT)=4, NDIM, NSPLIT=4) = 1024 CTAs of 128 threads
__global__ void __launch_bounds__(TPB) k_main(const float* __restrict__ ref,
                                              const float* __restrict__ alpha,
                                              int R) {
    const int d   = blockIdx.y;
    const int z   = blockIdx.z;
    const int lo0 = g_choff[d];
    const int len = g_choff[d + 1] - lo0;
    const int lo  = lo0 + (len * z) / NSPLIT;
    const int hi  = lo0 + (len * (z + 1)) / NSPLIT;
    const int tid = threadIdx.x;
    const int r0  = blockIdx.x * (TPB * RPT) + tid;

    const float negC = -__ldg(alpha) * LOG2E;
    const float f0 = __ldg(ref + r0),           f1 = __ldg(ref + r0 + TPB);
    const float f2 = __ldg(ref + r0 + 2 * TPB), f3 = __ldg(ref + r0 + 3 * TPB);
    const ull rr01 = pack2(f0, f1);
    const ull rr23 = pack2(f2, f3);
    const ull A01  = pack2(negC * f0 * f0, negC * f1 * f1);  // A = negC*r^2
    const ull A23  = pack2(negC * f2 * f2, negC * f3 * f3);

    ull ws01 = 0, wsv01 = 0, wc01 = 0, wcv01 = 0;
    ull ws23 = 0, wsv23 = 0, wc23 = 0, wcv23 = 0;

#pragma unroll 4
    for (int i = lo; i < hi; i++) {
        ulonglong2 bc = __ldg(&g_bc[i]);      // {B,B},{C,C}
        ull vp = __ldg(&g_vv[i]);             // {v,v}

        ull pc01 = add2(bc.y, A01);           // C + A
        ull pc23 = add2(bc.y, A23);
        ull g01  = fma2(bc.x, rr01, pc01);    // arg = B*r + (C+A) = negC*(r-t)^2
        ull g23  = fma2(bc.x, rr23, pc23);

        float a0, a1, a2, a3;
        unpack2(g01, a0, a1);
        unpack2(g23, a2, a3);
        ull e01 = pack2(ex2f(a0), ex2f(a1));  // e = exp(-a*dt^2)
        ull e23 = pack2(ex2f(a2), ex2f(a3));

        // e^10 = ((e^2)^2)^2 * e^2
        ull t2a = mul2(e01, e01);
        ull t4a = mul2(t2a, t2a);
        ull t8a = mul2(t4a, t4a);
        ull ec01 = mul2(t8a, t2a);
        ull t2b = mul2(e23, e23);
        ull t4b = mul2(t2b, t2b);
        ull t8b = mul2(t4b, t4b);
        ull ec23 = mul2(t8b, t2b);

        ws01  = add2(ws01, e01);
        wsv01 = fma2(e01, vp, wsv01);
        wc01  = add2(wc01, ec01);
        wcv01 = fma2(ec01, vp, wcv01);
        ws23  = add2(ws23, e23);
        wsv23 = fma2(e23, vp, wsv23);
        wc23  = add2(wc23, ec23);
        wcv23 = fma2(ec23, vp, wcv23);
    }

    float x0, x1;
    const int base = d * R + r0;
    unpack2(ws01,  x0, x1); g_Sws [z][base] = x0; g_Sws [z][base + TPB] = x1;
    unpack2(ws23,  x0, x1); g_Sws [z][base + 2 * TPB] = x0; g_Sws [z][base + 3 * TPB] = x1;
    unpack2(wsv01, x0, x1); g_Swsv[z][base] = x0; g_Swsv[z][base + TPB] = x1;
    unpack2(wsv23, x0, x1); g_Swsv[z][base + 2 * TPB] = x0; g_Swsv[z][base + 3 * TPB] = x1;
    unpack2(wc01,  x0, x1); g_Swc [z][base] = x0; g_Swc [z][base + TPB] = x1;
    unpack2(wc23,  x0, x1); g_Swc [z][base + 2 * TPB] = x0; g_Swc [z][base + 3 * TPB] = x1;
    unpack2(wcv01, x0, x1); g_Swcv[z][base] = x0; g_Swcv[z][base + TPB] = x1;
    unpack2(wcv23, x0, x1); g_Swcv[z][base + 2 * TPB] = x0; g_Swcv[z][base + 3 * TPB] = x1;
}

// ---------------- finalize: 512 blocks x 256 thr, 4 r's per block ----------------
__global__ void __launch_bounds__(256) k_finalize(const float* __restrict__ rho,
                                                  float* __restrict__ out,
                                                  int R, float Rinv) {
    __shared__ float s_lam[4][NDIM + 1];
    __shared__ float s_ksv[4][NDIM + 1];
    __shared__ float s_coa[4][NDIM + 1];
    __shared__ float s_den[4];

    const int tid = threadIdx.x;
    const int r0  = blockIdx.x * 4;

    // staging: thread -> (d = tid>>2, rl = tid&3); 16B-run global loads, L2-resident
    {
        const int d   = tid >> 2;
        const int rl  = tid & 3;
        const int idx = d * R + r0 + rl;
        const int cnt = g_choff[d + 1] - g_choff[d];
        const float ec = EPS * (float)(cnt + 1);
        const float ev = EPS * g_sumv[d];
        float lam_s = g_Sws [0][idx] + g_Sws [1][idx] + g_Sws [2][idx] + g_Sws [3][idx] + ec;
        float ksv   = g_Swsv[0][idx] + g_Swsv[1][idx] + g_Swsv[2][idx] + g_Swsv[3][idx] + ev;
        float lam_c = g_Swc [0][idx] + g_Swc [1][idx] + g_Swc [2][idx] + g_Swc [3][idx] + ec;
        float kcv   = g_Swcv[0][idx] + g_Swcv[1][idx] + g_Swcv[2][idx] + g_Swcv[3][idx] + ev;
        s_lam[rl][d] = lam_s;
        s_ksv[rl][d] = ksv;
        s_coa[rl][d] = __fdividef(kcv, lam_c);
    }
    __syncthreads();

    // denom: warp w (<4) reduces s_lam[w][0..63] via shfl
    {
        const int wid  = tid >> 5;
        const int lane = tid & 31;
        if (wid < 4) {
            float p = s_lam[wid][lane] + s_lam[wid][lane + 32];
            p += __shfl_xor_sync(0xffffffffu, p, 16);
            p += __shfl_xor_sync(0xffffffffu, p, 8);
            p += __shfl_xor_sync(0xffffffffu, p, 4);
            p += __shfl_xor_sync(0xffffffffu, p, 2);
            p += __shfl_xor_sync(0xffffffffu, p, 1);
            if (lane == 0) s_den[wid] = p;
        }
    }
    __syncthreads();

    // compute: thread -> (d = tid&63, rl = tid>>6); rho via L1-broadcast __ldg
    const int d  = tid & 63;
    const int rl = tid >> 6;
    float acc = 0.0f;
#pragma unroll
    for (int k = 0; k < NDIM; k++)
        acc = fmaf(s_ksv[rl][k], __ldg(&rho[k * NDIM + d]), acc);
    const float cr = __fdividef(acc, s_den[rl]);

    const int r = r0 + rl;
    float* o = out + (long long)r * (3 * NDIM);
    o[d]            = s_lam[rl][d] * Rinv;   // lam
    o[NDIM + d]     = cr;                    // cross
    o[2 * NDIM + d] = s_coa[rl][d] - cr;     // transient
}

// ---------------- launch ----------------
extern "C" void kernel_launch(void* const* d_in, const int* in_sizes, int n_in,
                              void* d_out, int out_size) {
    const float* S     = (const float*)d_in[0];
    const float* ref   = (const float*)d_in[1];
    const float* alpha = (const float*)d_in[2];
    const float* rho   = (const float*)d_in[3];
    const int n = in_sizes[0] / 3;
    const int R = in_sizes[1];
    int nchunks = (n + 255) / 256;
    if (nchunks > MAXCHUNKS) nchunks = MAXCHUNKS;

    k_hist<<<nchunks, 256>>>(S, n);
    k_scatter<<<nchunks, 256>>>(S, alpha, n, nchunks);

    dim3 g(R / (TPB * RPT), NDIM, NSPLIT);
    k_main<<<g, TPB>>>(ref, alpha, R);

    k_finalize<<<R / 4, 256>>>(rho, (float*)d_out, R, 1.0f / (float)R);
}